// round 11
// baseline (speedup 1.0000x reference)
#include <cuda_runtime.h>
#include <cuda_fp16.h>
#include <cstdint>

#define DI __device__ __forceinline__

// ---------------- problem dims ----------------
constexpr int Mdim = 16384;   // B*S
constexpr int Kdim = 2048;    // IN
constexpr int Ndim = 2048;    // OUT
constexpr int LR   = 128;     // L*R
constexpr int Rr   = 32;

// ---------------- scratch ----------------
__device__ uint4 g_xh_raw[(size_t)Mdim * Kdim * 2 / 16];   // fp16 x      (64 MB)
__device__ uint4 g_wh_raw[(size_t)Ndim * Kdim * 2 / 16];   // fp16 W_eff  (8 MB)

// ---------------- PTX helpers (family-portable only) ----------------
DI uint32_t smem_u32(const void* p) {
    uint32_t a;
    asm("{ .reg .u64 t; cvta.to.shared.u64 t, %1; cvt.u32.u64 %0, t; }" : "=r"(a) : "l"(p));
    return a;
}
DI void cp_async16(uint32_t dst, const void* src) {
    asm volatile("cp.async.cg.shared.global [%0], [%1], 16;" :: "r"(dst), "l"(src) : "memory");
}
DI void cp_commit() { asm volatile("cp.async.commit_group;" ::: "memory"); }
template <int Nn> DI void cp_wait() { asm volatile("cp.async.wait_group %0;" :: "n"(Nn) : "memory"); }

DI void ldmatrix_x4(uint32_t* r, uint32_t addr) {
    asm volatile("ldmatrix.sync.aligned.m8n8.x4.shared.b16 {%0,%1,%2,%3}, [%4];"
                 : "=r"(r[0]), "=r"(r[1]), "=r"(r[2]), "=r"(r[3]) : "r"(addr));
}
DI void mma16816(float* c, const uint32_t* a, uint32_t b0, uint32_t b1) {
    asm volatile(
        "mma.sync.aligned.m16n8k16.row.col.f32.f16.f16.f32 "
        "{%0,%1,%2,%3}, {%4,%5,%6,%7}, {%8,%9}, {%0,%1,%2,%3};"
        : "+f"(c[0]), "+f"(c[1]), "+f"(c[2]), "+f"(c[3])
        : "r"(a[0]), "r"(a[1]), "r"(a[2]), "r"(a[3]), "r"(b0), "r"(b1));
}
DI uint32_t tile_off(int row, int c) { return (uint32_t)(row * 128) + (uint32_t)(((c ^ (row & 7)) << 4)); }
DI uint32_t swz128(uint32_t b) { return b ^ ((b >> 3) & 0x70); }

// ============================================================
// Pre-pass 1: x fp32 -> fp16 (no smem, full occupancy; 27.5us measured)
// ============================================================
__global__ void __launch_bounds__(256) k_convert(const float* __restrict__ x) {
    size_t i = (size_t)blockIdx.x * 256 + threadIdx.x;
    const size_t stride = (size_t)gridDim.x * 256;
    const float4* x4 = (const float4*)x;
    uint2* o4 = (uint2*)g_xh_raw;
    const size_t n4 = (size_t)Mdim * Kdim / 4;
    for (; i < n4; i += stride) {
        float4 v = x4[i];
        __half2 a = __floats2half2_rn(v.x, v.y);
        __half2 b = __floats2half2_rn(v.z, v.w);
        uint2 u;
        u.x = *(uint32_t*)&a;
        u.y = *(uint32_t*)&b;
        o4[i] = u;
    }
}

// ============================================================
// Pre-pass 2: W_eff = W + sum_l s_l * up_l @ down_l -> fp16
// ============================================================
constexpr int US_STRIDE = 68;
constexpr int PREP_SMEM = (LR * US_STRIDE + LR * 64) * 4;  // 67584 B

__global__ void __launch_bounds__(256) k_weff(const float* __restrict__ weight,
                                              const float* __restrict__ downs,
                                              const float* __restrict__ ups,
                                              const float* __restrict__ scales) {
    extern __shared__ float wsm[];
    float* Us = wsm;                   // [128][US_STRIDE]
    float* Ds = wsm + LR * US_STRIDE;  // [128][64]
    const int I0 = (blockIdx.x & 31) * 64;
    const int O0 = (blockIdx.x >> 5) * 64;
    const int tid = threadIdx.x;

    {
        const int r = tid & 31, ob = tid >> 5;
#pragma unroll
        for (int l = 0; l < 4; l++) {
            float s = scales[l];
            const float* up_l = ups + (size_t)l * Ndim * Rr;
#pragma unroll
            for (int it = 0; it < 8; it++) {
                int o = it * 8 + ob;
                Us[(l * 32 + r) * US_STRIDE + o] = s * up_l[(size_t)(O0 + o) * Rr + r];
            }
        }
    }
    for (int c = tid; c < LR * 16; c += 256) {
        int k = c >> 4, f = c & 15;
        *(float4*)&Ds[k * 64 + f * 4] = *(const float4*)&downs[(size_t)k * Kdim + I0 + f * 4];
    }
    __syncthreads();

    const int to = tid >> 4, ti = tid & 15;
    float acc[4][4];
#pragma unroll
    for (int a = 0; a < 4; a++)
#pragma unroll
        for (int b = 0; b < 4; b++) acc[a][b] = 0.f;

#pragma unroll 4
    for (int k = 0; k < LR; k++) {
        float4 u = *(const float4*)&Us[k * US_STRIDE + to * 4];
        float4 d = *(const float4*)&Ds[k * 64 + ti * 4];
        float uu[4] = {u.x, u.y, u.z, u.w};
        float dd[4] = {d.x, d.y, d.z, d.w};
#pragma unroll
        for (int a = 0; a < 4; a++)
#pragma unroll
            for (int b = 0; b < 4; b++) acc[a][b] += uu[a] * dd[b];
    }

    __half* gw = (__half*)g_wh_raw;
#pragma unroll
    for (int a = 0; a < 4; a++) {
        int o = O0 + to * 4 + a;
        float4 wv = *(const float4*)&weight[(size_t)o * Kdim + I0 + ti * 4];
        __half2 p0 = __floats2half2_rn(acc[a][0] + wv.x, acc[a][1] + wv.y);
        __half2 p1 = __floats2half2_rn(acc[a][2] + wv.z, acc[a][3] + wv.w);
        uint2 u;
        u.x = *(uint32_t*)&p0;
        u.y = *(uint32_t*)&p1;
        *(uint2*)&gw[(size_t)o * Kdim + I0 + ti * 4] = u;
    }
}

// ============================================================
// Main GEMM: y = xh @ Wh^T + bias  (R2 structure + per-warp ks stagger)
//   mma.sync.m16n8k16 fp32 acc, BM=BN=128, BK=64, 3-stage cp.async,
//   256 threads (8 warps 2x4, warp tile 64x32), 2 CTAs/SM.
//   Each warp walks the 4 k16-sub-steps in a rotated order
//   ((ks + wid) & 3) so the 4 warps per SMSP are phase-decorrelated:
//   some warp always has an issuable HMMA while others are in LDSM.
// ============================================================
constexpr int BK = 64;
constexpr int STAGES = 3;
constexpr int NK = Kdim / BK;                    // 32
constexpr int AB_BYTES = 128 * 128;              // 16 KB
constexpr int STG_BYTES = 2 * AB_BYTES;          // 32 KB
constexpr int GEMM_SMEM = STAGES * STG_BYTES;    // 96 KB

__global__ void __launch_bounds__(256, 2) k_gemm(const float* __restrict__ bias,
                                                 float* __restrict__ out) {
    extern __shared__ char smem[];
    const uint32_t sb = smem_u32(smem);
    const int tid = threadIdx.x;
    const int wid = tid >> 5, lane = tid & 31;
    const int M0 = blockIdx.y * 128, N0 = blockIdx.x * 128;

    const int warp_m = (wid & 1) * 64;     // 2 warps along M
    const int warp_n = (wid >> 1) * 32;    // 4 warps along N
    const int koff = wid & 3;              // per-warp ks rotation

    const __half* gA = (const __half*)g_xh_raw;
    const __half* gB = (const __half*)g_wh_raw;

    auto load_stage = [&](int s, int kk) {
        const uint32_t base = sb + s * STG_BYTES;
        const int k0 = kk * BK;
#pragma unroll
        for (int it = 0; it < 4; it++) {
            int c = tid + it * 256;
            int row = c >> 3, col = c & 7;
            cp_async16(base + swz128(row * 128 + col * 16),
                       gA + (size_t)(M0 + row) * Kdim + k0 + col * 8);
        }
#pragma unroll
        for (int it = 0; it < 4; it++) {
            int c = tid + it * 256;
            int row = c >> 3, col = c & 7;
            cp_async16(base + AB_BYTES + swz128(row * 128 + col * 16),
                       gB + (size_t)(N0 + row) * Kdim + k0 + col * 8);
        }
    };

    float acc[4][4][4];
#pragma unroll
    for (int mt = 0; mt < 4; mt++)
#pragma unroll
        for (int nt = 0; nt < 4; nt++)
#pragma unroll
            for (int c = 0; c < 4; c++) acc[mt][nt][c] = 0.f;

    // prologue
    load_stage(0, 0); cp_commit();
    load_stage(1, 1); cp_commit();

    const int lane15 = lane & 15;
    const int laneHi = lane >> 4;
    int rowA[4], rowB[2];
#pragma unroll
    for (int mt = 0; mt < 4; mt++) rowA[mt] = warp_m + mt * 16 + lane15;
#pragma unroll
    for (int np = 0; np < 2; np++) rowB[np] = warp_n + np * 16 + lane15;

    for (int k = 0; k < NK; k++) {
        cp_wait<STAGES - 2>();
        __syncthreads();

        const int kn = k + STAGES - 1;
        if (kn < NK) load_stage(kn % STAGES, kn);
        cp_commit();

        const int s = k % STAGES;
        const uint32_t Ab = sb + s * STG_BYTES;
        const uint32_t Bb = Ab + AB_BYTES;

#pragma unroll
        for (int ks = 0; ks < 4; ks++) {   // rotated per warp: decorrelate SMSP phases
            const int kso = (ks + koff) & 3;
            uint32_t a[4][4], b[2][4];
#pragma unroll
            for (int mt = 0; mt < 4; mt++)
                ldmatrix_x4(a[mt], Ab + tile_off(rowA[mt], kso * 2 + laneHi));
#pragma unroll
            for (int np = 0; np < 2; np++)
                ldmatrix_x4(b[np], Bb + tile_off(rowB[np], kso * 2 + laneHi));
#pragma unroll
            for (int mt = 0; mt < 4; mt++)
#pragma unroll
                for (int nt = 0; nt < 4; nt++) {
                    const int np = nt >> 1, half = nt & 1;
                    mma16816(acc[mt][nt], a[mt], b[np][half], b[np][2 + half]);
                }
        }
    }

    // epilogue: acc -> out with bias
    const int gq = lane >> 2, rq = lane & 3;
#pragma unroll
    for (int mt = 0; mt < 4; mt++) {
#pragma unroll
        for (int nt = 0; nt < 4; nt++) {
            int m = M0 + warp_m + mt * 16 + gq;
            int n = N0 + warp_n + nt * 8 + rq * 2;
            float2 bv = *(const float2*)&bias[n];
            float2 v0, v1;
            v0.x = acc[mt][nt][0] + bv.x;
            v0.y = acc[mt][nt][1] + bv.y;
            v1.x = acc[mt][nt][2] + bv.x;
            v1.y = acc[mt][nt][3] + bv.y;
            *(float2*)&out[(size_t)m * Ndim + n] = v0;
            *(float2*)&out[(size_t)(m + 8) * Ndim + n] = v1;
        }
    }
}

// ============================================================
// launch
// ============================================================
extern "C" void kernel_launch(void* const* d_in, const int* in_sizes, int n_in,
                              void* d_out, int out_size) {
    const float* x      = (const float*)d_in[0];
    const float* weight = (const float*)d_in[1];
    const float* bias   = (const float*)d_in[2];
    const float* downs  = (const float*)d_in[3];
    const float* ups    = (const float*)d_in[4];
    const float* scales = (const float*)d_in[5];
    float* out = (float*)d_out;

    cudaFuncSetAttribute(k_gemm, cudaFuncAttributeMaxDynamicSharedMemorySize, GEMM_SMEM);
    cudaFuncSetAttribute(k_weff, cudaFuncAttributeMaxDynamicSharedMemorySize, PREP_SMEM);

    k_convert<<<8192, 256>>>(x);
    k_weff<<<(Ndim / 64) * (Kdim / 64), 256, PREP_SMEM>>>(weight, downs, ups, scales);
    k_gemm<<<dim3(Ndim / 128, Mdim / 128), 256, GEMM_SMEM>>>(bias, out);
}

// round 12
// speedup vs baseline: 1.0525x; 1.0525x over previous
#include <cuda_runtime.h>
#include <cuda_fp16.h>
#include <cstdint>

#define DI __device__ __forceinline__

// ---------------- problem dims ----------------
constexpr int Mdim = 16384;   // B*S
constexpr int Kdim = 2048;    // IN
constexpr int Ndim = 2048;    // OUT
constexpr int LR   = 128;     // L*R
constexpr int Rr   = 32;

// ---------------- scratch ----------------
__device__ uint4 g_xh_raw[(size_t)Mdim * Kdim * 2 / 16];   // fp16 x      (64 MB)
__device__ uint4 g_wh_raw[(size_t)Ndim * Kdim * 2 / 16];   // fp16 W_eff  (8 MB)

// ---------------- PTX helpers (family-portable only) ----------------
DI uint32_t smem_u32(const void* p) {
    uint32_t a;
    asm("{ .reg .u64 t; cvta.to.shared.u64 t, %1; cvt.u32.u64 %0, t; }" : "=r"(a) : "l"(p));
    return a;
}
DI void cp_async16(uint32_t dst, const void* src) {
    asm volatile("cp.async.cg.shared.global [%0], [%1], 16;" :: "r"(dst), "l"(src) : "memory");
}
DI void cp_commit() { asm volatile("cp.async.commit_group;" ::: "memory"); }
template <int Nn> DI void cp_wait() { asm volatile("cp.async.wait_group %0;" :: "n"(Nn) : "memory"); }

DI void ldmatrix_x4(uint32_t* r, uint32_t addr) {
    asm volatile("ldmatrix.sync.aligned.m8n8.x4.shared.b16 {%0,%1,%2,%3}, [%4];"
                 : "=r"(r[0]), "=r"(r[1]), "=r"(r[2]), "=r"(r[3]) : "r"(addr));
}
DI void mma16816(float* c, const uint32_t* a, uint32_t b0, uint32_t b1) {
    asm volatile(
        "mma.sync.aligned.m16n8k16.row.col.f32.f16.f16.f32 "
        "{%0,%1,%2,%3}, {%4,%5,%6,%7}, {%8,%9}, {%0,%1,%2,%3};"
        : "+f"(c[0]), "+f"(c[1]), "+f"(c[2]), "+f"(c[3])
        : "r"(a[0]), "r"(a[1]), "r"(a[2]), "r"(a[3]), "r"(b0), "r"(b1));
}
DI uint32_t swz128(uint32_t b) { return b ^ ((b >> 3) & 0x70); }

// ============================================================
// Pre-pass 1: x fp32 -> fp16 (no smem; 26.6us measured, ~HBM roofline)
// ============================================================
__global__ void __launch_bounds__(256) k_convert(const float* __restrict__ x) {
    size_t i = (size_t)blockIdx.x * 256 + threadIdx.x;
    const size_t stride = (size_t)gridDim.x * 256;
    const float4* x4 = (const float4*)x;
    uint2* o4 = (uint2*)g_xh_raw;
    const size_t n4 = (size_t)Mdim * Kdim / 4;
    for (; i < n4; i += stride) {
        float4 v = x4[i];
        __half2 a = __floats2half2_rn(v.x, v.y);
        __half2 b = __floats2half2_rn(v.z, v.w);
        uint2 u;
        u.x = *(uint32_t*)&a;
        u.y = *(uint32_t*)&b;
        o4[i] = u;
    }
}

// ============================================================
// Pre-pass 2: W_eff = W + sum_l s_l * up_l @ down_l -> fp16
// ============================================================
constexpr int US_STRIDE = 68;
constexpr int PREP_SMEM = (LR * US_STRIDE + LR * 64) * 4;  // 67584 B

__global__ void __launch_bounds__(256) k_weff(const float* __restrict__ weight,
                                              const float* __restrict__ downs,
                                              const float* __restrict__ ups,
                                              const float* __restrict__ scales) {
    extern __shared__ float wsm[];
    float* Us = wsm;                   // [128][US_STRIDE]
    float* Ds = wsm + LR * US_STRIDE;  // [128][64]
    const int I0 = (blockIdx.x & 31) * 64;
    const int O0 = (blockIdx.x >> 5) * 64;
    const int tid = threadIdx.x;

    {
        const int r = tid & 31, ob = tid >> 5;
#pragma unroll
        for (int l = 0; l < 4; l++) {
            float s = scales[l];
            const float* up_l = ups + (size_t)l * Ndim * Rr;
#pragma unroll
            for (int it = 0; it < 8; it++) {
                int o = it * 8 + ob;
                Us[(l * 32 + r) * US_STRIDE + o] = s * up_l[(size_t)(O0 + o) * Rr + r];
            }
        }
    }
    for (int c = tid; c < LR * 16; c += 256) {
        int k = c >> 4, f = c & 15;
        *(float4*)&Ds[k * 64 + f * 4] = *(const float4*)&downs[(size_t)k * Kdim + I0 + f * 4];
    }
    __syncthreads();

    const int to = tid >> 4, ti = tid & 15;
    float acc[4][4];
#pragma unroll
    for (int a = 0; a < 4; a++)
#pragma unroll
        for (int b = 0; b < 4; b++) acc[a][b] = 0.f;

#pragma unroll 4
    for (int k = 0; k < LR; k++) {
        float4 u = *(const float4*)&Us[k * US_STRIDE + to * 4];
        float4 d = *(const float4*)&Ds[k * 64 + ti * 4];
        float uu[4] = {u.x, u.y, u.z, u.w};
        float dd[4] = {d.x, d.y, d.z, d.w};
#pragma unroll
        for (int a = 0; a < 4; a++)
#pragma unroll
            for (int b = 0; b < 4; b++) acc[a][b] += uu[a] * dd[b];
    }

    __half* gw = (__half*)g_wh_raw;
#pragma unroll
    for (int a = 0; a < 4; a++) {
        int o = O0 + to * 4 + a;
        float4 wv = *(const float4*)&weight[(size_t)o * Kdim + I0 + ti * 4];
        __half2 p0 = __floats2half2_rn(acc[a][0] + wv.x, acc[a][1] + wv.y);
        __half2 p1 = __floats2half2_rn(acc[a][2] + wv.z, acc[a][3] + wv.w);
        uint2 u;
        u.x = *(uint32_t*)&p0;
        u.y = *(uint32_t*)&p1;
        *(uint2*)&gw[(size_t)o * Kdim + I0 + ti * 4] = u;
    }
}

// ============================================================
// Main GEMM (exact R2 structure — best measured: 359.5us):
//   mma.sync.m16n8k16 fp32 acc, BM=BN=128, BK=64, 3-stage cp.async,
//   256 threads (8 warps 2x4, warp tile 64x32), 2 CTAs/SM.
// ============================================================
constexpr int BK = 64;
constexpr int STAGES = 3;
constexpr int NK = Kdim / BK;                    // 32
constexpr int AB_BYTES = 128 * 128;              // 16 KB
constexpr int STG_BYTES = 2 * AB_BYTES;          // 32 KB
constexpr int GEMM_SMEM = STAGES * STG_BYTES;    // 96 KB

__global__ void __launch_bounds__(256, 2) k_gemm(const float* __restrict__ bias,
                                                 float* __restrict__ out) {
    extern __shared__ char smem[];
    const uint32_t sb = smem_u32(smem);
    const int tid = threadIdx.x;
    const int wid = tid >> 5, lane = tid & 31;
    const int M0 = blockIdx.y * 128, N0 = blockIdx.x * 128;

    const int warp_m = (wid & 1) * 64;     // 2 warps along M
    const int warp_n = (wid >> 1) * 32;    // 4 warps along N

    const __half* gA = (const __half*)g_xh_raw;
    const __half* gB = (const __half*)g_wh_raw;

    auto load_stage = [&](int s, int kk) {
        const uint32_t base = sb + s * STG_BYTES;
        const int k0 = kk * BK;
#pragma unroll
        for (int it = 0; it < 4; it++) {
            int c = tid + it * 256;
            int row = c >> 3, col = c & 7;
            cp_async16(base + swz128(row * 128 + col * 16),
                       gA + (size_t)(M0 + row) * Kdim + k0 + col * 8);
        }
#pragma unroll
        for (int it = 0; it < 4; it++) {
            int c = tid + it * 256;
            int row = c >> 3, col = c & 7;
            cp_async16(base + AB_BYTES + swz128(row * 128 + col * 16),
                       gB + (size_t)(N0 + row) * Kdim + k0 + col * 8);
        }
    };

    float acc[4][4][4];
#pragma unroll
    for (int mt = 0; mt < 4; mt++)
#pragma unroll
        for (int nt = 0; nt < 4; nt++)
#pragma unroll
            for (int c = 0; c < 4; c++) acc[mt][nt][c] = 0.f;

    // prologue
    load_stage(0, 0); cp_commit();
    load_stage(1, 1); cp_commit();

    const int lane15 = lane & 15;
    const int laneHi = lane >> 4;

    for (int k = 0; k < NK; k++) {
        cp_wait<STAGES - 2>();
        __syncthreads();

        const int kn = k + STAGES - 1;
        if (kn < NK) load_stage(kn % STAGES, kn);
        cp_commit();

        const int s = k % STAGES;
        const uint32_t Ab = sb + s * STG_BYTES;
        const uint32_t Bb = Ab + AB_BYTES;

#pragma unroll
        for (int ks = 0; ks < 4; ks++) {   // 4 x k16 per BK=64
            uint32_t a[4][4], b[2][4];
#pragma unroll
            for (int mt = 0; mt < 4; mt++) {
                int row = warp_m + mt * 16 + lane15;
                ldmatrix_x4(a[mt], Ab + swz128(row * 128 + (ks * 2 + laneHi) * 16));
            }
#pragma unroll
            for (int np = 0; np < 2; np++) {
                int row = warp_n + np * 16 + lane15;
                ldmatrix_x4(b[np], Bb + swz128(row * 128 + (ks * 2 + laneHi) * 16));
            }
#pragma unroll
            for (int mt = 0; mt < 4; mt++)
#pragma unroll
                for (int nt = 0; nt < 4; nt++) {
                    const int np = nt >> 1, half = nt & 1;
                    mma16816(acc[mt][nt], a[mt], b[np][half], b[np][2 + half]);
                }
        }
    }

    // epilogue: acc -> out with bias
    const int gq = lane >> 2, rq = lane & 3;
#pragma unroll
    for (int mt = 0; mt < 4; mt++) {
#pragma unroll
        for (int nt = 0; nt < 4; nt++) {
            int m = M0 + warp_m + mt * 16 + gq;
            int n = N0 + warp_n + nt * 8 + rq * 2;
            float2 bv = *(const float2*)&bias[n];
            float2 v0, v1;
            v0.x = acc[mt][nt][0] + bv.x;
            v0.y = acc[mt][nt][1] + bv.y;
            v1.x = acc[mt][nt][2] + bv.x;
            v1.y = acc[mt][nt][3] + bv.y;
            *(float2*)&out[(size_t)m * Ndim + n] = v0;
            *(float2*)&out[(size_t)(m + 8) * Ndim + n] = v1;
        }
    }
}

// ============================================================
// launch
// ============================================================
extern "C" void kernel_launch(void* const* d_in, const int* in_sizes, int n_in,
                              void* d_out, int out_size) {
    const float* x      = (const float*)d_in[0];
    const float* weight = (const float*)d_in[1];
    const float* bias   = (const float*)d_in[2];
    const float* downs  = (const float*)d_in[3];
    const float* ups    = (const float*)d_in[4];
    const float* scales = (const float*)d_in[5];
    float* out = (float*)d_out;

    cudaFuncSetAttribute(k_gemm, cudaFuncAttributeMaxDynamicSharedMemorySize, GEMM_SMEM);
    cudaFuncSetAttribute(k_weff, cudaFuncAttributeMaxDynamicSharedMemorySize, PREP_SMEM);

    k_convert<<<8192, 256>>>(x);
    k_weff<<<(Ndim / 64) * (Kdim / 64), 256, PREP_SMEM>>>(weight, downs, ups, scales);
    k_gemm<<<dim3(Ndim / 128, Mdim / 128), 256, GEMM_SMEM>>>(bias, out);
}

// round 14
// speedup vs baseline: 1.1461x; 1.0889x over previous
#include <cuda_runtime.h>
#include <cuda_fp16.h>
#include <cstdint>

#define DI __device__ __forceinline__

// ---------------- problem dims ----------------
constexpr int Mdim = 16384;   // B*S
constexpr int Kdim = 2048;    // IN
constexpr int Ndim = 2048;    // OUT
constexpr int LR   = 128;     // L*R
constexpr int Rr   = 32;

// ---------------- scratch ----------------
__device__ uint4 g_xh_raw[(size_t)Mdim * Kdim * 2 / 16];   // fp16 x      (64 MB)
__device__ uint4 g_wh_raw[(size_t)Ndim * Kdim * 2 / 16];   // fp16 W_eff  (8 MB)
__device__ uint4 g_ah_raw[(size_t)Ndim * LR * 2 / 16];     // fp16 scaled ups^T [o][k] (512 KB)
__device__ uint4 g_bh_raw[(size_t)Kdim * LR * 2 / 16];     // fp16 downs^T [i][k]     (512 KB)

// ---------------- PTX helpers (family-portable only) ----------------
DI uint32_t smem_u32(const void* p) {
    uint32_t a;
    asm("{ .reg .u64 t; cvta.to.shared.u64 t, %1; cvt.u32.u64 %0, t; }" : "=r"(a) : "l"(p));
    return a;
}
DI void cp_async16(uint32_t dst, const void* src) {
    asm volatile("cp.async.cg.shared.global [%0], [%1], 16;" :: "r"(dst), "l"(src) : "memory");
}
DI void cp_commit() { asm volatile("cp.async.commit_group;" ::: "memory"); }
template <int Nn> DI void cp_wait() { asm volatile("cp.async.wait_group %0;" :: "n"(Nn) : "memory"); }

DI void ldmatrix_x4(uint32_t* r, uint32_t addr) {
    asm volatile("ldmatrix.sync.aligned.m8n8.x4.shared.b16 {%0,%1,%2,%3}, [%4];"
                 : "=r"(r[0]), "=r"(r[1]), "=r"(r[2]), "=r"(r[3]) : "r"(addr));
}
DI void mma16816(float* c, const uint32_t* a, uint32_t b0, uint32_t b1) {
    asm volatile(
        "mma.sync.aligned.m16n8k16.row.col.f32.f16.f16.f32 "
        "{%0,%1,%2,%3}, {%4,%5,%6,%7}, {%8,%9}, {%0,%1,%2,%3};"
        : "+f"(c[0]), "+f"(c[1]), "+f"(c[2]), "+f"(c[3])
        : "r"(a[0]), "r"(a[1]), "r"(a[2]), "r"(a[3]), "r"(b0), "r"(b1));
}
DI uint32_t swz128(uint32_t b) { return b ^ ((b >> 3) & 0x70); }

// ============================================================
// k_prep2 — one no-smem kernel, three block ranges:
//   [0, 4096)            : x fp32 -> fp16 (grid-stride, HBM-bound)
//   [4096, 4096+128)     : Ah[o][l*32+r] = half(scales[l] * ups[l][o][r])
//   [4224, 4224+64)      : Bh[i][k] = half(downs[k][i])
// ============================================================
constexpr int CONV_BLOCKS = 4096;
constexpr int ABUILD_BLOCKS = 128;   // 2048*16 threads / 256
constexpr int BBUILD_BLOCKS = 64;    // 2048*8  threads / 256
constexpr int PREP2_BLOCKS = CONV_BLOCKS + ABUILD_BLOCKS + BBUILD_BLOCKS;

__global__ void __launch_bounds__(256) k_prep2(const float* __restrict__ x,
                                               const float* __restrict__ downs,
                                               const float* __restrict__ ups,
                                               const float* __restrict__ scales) {
    const int tid = threadIdx.x;
    const int bx = blockIdx.x;

    if (bx < CONV_BLOCKS) {
        // ---- x conversion ----
        size_t i = (size_t)bx * 256 + tid;
        const size_t stride = (size_t)CONV_BLOCKS * 256;
        const float4* x4 = (const float4*)x;
        uint2* o4 = (uint2*)g_xh_raw;
        const size_t n4 = (size_t)Mdim * Kdim / 4;
        for (; i < n4; i += stride) {
            float4 v = x4[i];
            __half2 a = __floats2half2_rn(v.x, v.y);
            __half2 b = __floats2half2_rn(v.z, v.w);
            uint2 u;
            u.x = *(uint32_t*)&a;
            u.y = *(uint32_t*)&b;
            o4[i] = u;
        }
        return;
    }

    if (bx < CONV_BLOCKS + ABUILD_BLOCKS) {
        // ---- A build: Ah[o][l*32 + r] = half(scales[l] * ups[l][o][r]) ----
        // thread t handles 8 consecutive r for one (o, l, r-octet)
        int t = (bx - CONV_BLOCKS) * 256 + tid;   // 0 .. 2048*16-1
        int o = t >> 4;
        int q = t & 15;          // l (2b) x r-octet (2b)
        int l = q >> 2;
        int r0 = (q & 3) * 8;
        float s = scales[l];
        const float* up = ups + ((size_t)l * Ndim + o) * Rr + r0;
        float4 v0 = *(const float4*)(up);
        float4 v1 = *(const float4*)(up + 4);
        __half h[8];
        h[0] = __float2half_rn(s * v0.x); h[1] = __float2half_rn(s * v0.y);
        h[2] = __float2half_rn(s * v0.z); h[3] = __float2half_rn(s * v0.w);
        h[4] = __float2half_rn(s * v1.x); h[5] = __float2half_rn(s * v1.y);
        h[6] = __float2half_rn(s * v1.z); h[7] = __float2half_rn(s * v1.w);
        __half* A = (__half*)g_ah_raw;
        *(uint4*)&A[(size_t)o * LR + l * Rr + r0] = *(uint4*)h;
        return;
    }

    // ---- B build: Bh[i][k] = half(downs[k][i]), k-chunk of 16 per thread ----
    int t = (bx - CONV_BLOCKS - ABUILD_BLOCKS) * 256 + tid;   // 0 .. 2048*8-1
    int i = t >> 3;
    int k0 = (t & 7) * 16;
    __half h[16];
#pragma unroll
    for (int j = 0; j < 16; j++)
        h[j] = __float2half_rn(downs[(size_t)(k0 + j) * Kdim + i]);
    __half* B = (__half*)g_bh_raw;
    uint4* dst = (uint4*)&B[(size_t)i * LR + k0];
    dst[0] = ((uint4*)h)[0];
    dst[1] = ((uint4*)h)[1];
}

// ============================================================
// k_weff_mma: W_eff[o][i] = W[o][i] + sum_k Ah[o][k]*Bh[i][k]
//   M=o (2048), N=i (2048), K=128. 256 CTAs of 128x128 tiles.
//   Both BK=64 stages loaded up front (K=128 fits in 2 stages).
//   Epilogue: acc + W (fp32) -> fp16 into g_wh.
// ============================================================
constexpr int WF_AB = 128 * 128;          // bytes per operand per stage
constexpr int WF_STG = 2 * WF_AB;         // 32 KB
constexpr int WF_SMEM = 2 * WF_STG;       // 64 KB (2 stages)

__global__ void __launch_bounds__(256, 2) k_weff_mma(const float* __restrict__ weight) {
    extern __shared__ char smem[];
    const uint32_t sb = smem_u32(smem);
    const int tid = threadIdx.x;
    const int wid = tid >> 5, lane = tid & 31;
    const int M0 = blockIdx.y * 128, N0 = blockIdx.x * 128;

    const int warp_m = (wid & 1) * 64;
    const int warp_n = (wid >> 1) * 32;

    const __half* gA = (const __half*)g_ah_raw;
    const __half* gB = (const __half*)g_bh_raw;

    // load both K-stages
#pragma unroll
    for (int s = 0; s < 2; s++) {
        const uint32_t base = sb + s * WF_STG;
        const int k0 = s * 64;
#pragma unroll
        for (int it = 0; it < 4; it++) {
            int c = tid + it * 256;
            int row = c >> 3, col = c & 7;
            cp_async16(base + swz128(row * 128 + col * 16),
                       gA + (size_t)(M0 + row) * LR + k0 + col * 8);
        }
#pragma unroll
        for (int it = 0; it < 4; it++) {
            int c = tid + it * 256;
            int row = c >> 3, col = c & 7;
            cp_async16(base + WF_AB + swz128(row * 128 + col * 16),
                       gB + (size_t)(N0 + row) * LR + k0 + col * 8);
        }
    }
    cp_commit();
    cp_wait<0>();
    __syncthreads();

    float acc[4][4][4];
#pragma unroll
    for (int mt = 0; mt < 4; mt++)
#pragma unroll
        for (int nt = 0; nt < 4; nt++)
#pragma unroll
            for (int c = 0; c < 4; c++) acc[mt][nt][c] = 0.f;

    const int lane15 = lane & 15;
    const int laneHi = lane >> 4;

#pragma unroll
    for (int s = 0; s < 2; s++) {
        const uint32_t Ab = sb + s * WF_STG;
        const uint32_t Bb = Ab + WF_AB;
#pragma unroll
        for (int ks = 0; ks < 4; ks++) {
            uint32_t a[4][4], b[2][4];
#pragma unroll
            for (int mt = 0; mt < 4; mt++) {
                int row = warp_m + mt * 16 + lane15;
                ldmatrix_x4(a[mt], Ab + swz128(row * 128 + (ks * 2 + laneHi) * 16));
            }
#pragma unroll
            for (int np = 0; np < 2; np++) {
                int row = warp_n + np * 16 + lane15;
                ldmatrix_x4(b[np], Bb + swz128(row * 128 + (ks * 2 + laneHi) * 16));
            }
#pragma unroll
            for (int mt = 0; mt < 4; mt++)
#pragma unroll
                for (int nt = 0; nt < 4; nt++) {
                    const int np = nt >> 1, half = nt & 1;
                    mma16816(acc[mt][nt], a[mt], b[np][half], b[np][2 + half]);
                }
        }
    }

    // epilogue: W_eff = acc + W -> fp16
    __half* gw = (__half*)g_wh_raw;
    const int gq = lane >> 2, rq = lane & 3;
#pragma unroll
    for (int mt = 0; mt < 4; mt++) {
#pragma unroll
        for (int nt = 0; nt < 4; nt++) {
            int m = M0 + warp_m + mt * 16 + gq;       // o
            int n = N0 + warp_n + nt * 8 + rq * 2;    // i
            float2 w0 = *(const float2*)&weight[(size_t)m * Kdim + n];
            float2 w1 = *(const float2*)&weight[(size_t)(m + 8) * Kdim + n];
            __half2 p0 = __floats2half2_rn(acc[mt][nt][0] + w0.x, acc[mt][nt][1] + w0.y);
            __half2 p1 = __floats2half2_rn(acc[mt][nt][2] + w1.x, acc[mt][nt][3] + w1.y);
            *(uint32_t*)&gw[(size_t)m * Kdim + n] = *(uint32_t*)&p0;
            *(uint32_t*)&gw[(size_t)(m + 8) * Kdim + n] = *(uint32_t*)&p1;
        }
    }
}

// ============================================================
// Main GEMM (exact R2 structure — best measured):
//   mma.sync.m16n8k16 fp32 acc, BM=BN=128, BK=64, 3-stage cp.async,
//   256 threads (8 warps 2x4, warp tile 64x32), 2 CTAs/SM.
// ============================================================
constexpr int BK = 64;
constexpr int STAGES = 3;
constexpr int NK = Kdim / BK;                    // 32
constexpr int AB_BYTES = 128 * 128;              // 16 KB
constexpr int STG_BYTES = 2 * AB_BYTES;          // 32 KB
constexpr int GEMM_SMEM = STAGES * STG_BYTES;    // 96 KB

__global__ void __launch_bounds__(256, 2) k_gemm(const float* __restrict__ bias,
                                                 float* __restrict__ out) {
    extern __shared__ char smem[];
    const uint32_t sb = smem_u32(smem);
    const int tid = threadIdx.x;
    const int wid = tid >> 5, lane = tid & 31;
    const int M0 = blockIdx.y * 128, N0 = blockIdx.x * 128;

    const int warp_m = (wid & 1) * 64;
    const int warp_n = (wid >> 1) * 32;

    const __half* gA = (const __half*)g_xh_raw;
    const __half* gB = (const __half*)g_wh_raw;

    auto load_stage = [&](int s, int kk) {
        const uint32_t base = sb + s * STG_BYTES;
        const int k0 = kk * BK;
#pragma unroll
        for (int it = 0; it < 4; it++) {
            int c = tid + it * 256;
            int row = c >> 3, col = c & 7;
            cp_async16(base + swz128(row * 128 + col * 16),
                       gA + (size_t)(M0 + row) * Kdim + k0 + col * 8);
        }
#pragma unroll
        for (int it = 0; it < 4; it++) {
            int c = tid + it * 256;
            int row = c >> 3, col = c & 7;
            cp_async16(base + AB_BYTES + swz128(row * 128 + col * 16),
                       gB + (size_t)(N0 + row) * Kdim + k0 + col * 8);
        }
    };

    float acc[4][4][4];
#pragma unroll
    for (int mt = 0; mt < 4; mt++)
#pragma unroll
        for (int nt = 0; nt < 4; nt++)
#pragma unroll
            for (int c = 0; c < 4; c++) acc[mt][nt][c] = 0.f;

    load_stage(0, 0); cp_commit();
    load_stage(1, 1); cp_commit();

    const int lane15 = lane & 15;
    const int laneHi = lane >> 4;

    for (int k = 0; k < NK; k++) {
        cp_wait<STAGES - 2>();
        __syncthreads();

        const int kn = k + STAGES - 1;
        if (kn < NK) load_stage(kn % STAGES, kn);
        cp_commit();

        const int s = k % STAGES;
        const uint32_t Ab = sb + s * STG_BYTES;
        const uint32_t Bb = Ab + AB_BYTES;

#pragma unroll
        for (int ks = 0; ks < 4; ks++) {
            uint32_t a[4][4], b[2][4];
#pragma unroll
            for (int mt = 0; mt < 4; mt++) {
                int row = warp_m + mt * 16 + lane15;
                ldmatrix_x4(a[mt], Ab + swz128(row * 128 + (ks * 2 + laneHi) * 16));
            }
#pragma unroll
            for (int np = 0; np < 2; np++) {
                int row = warp_n + np * 16 + lane15;
                ldmatrix_x4(b[np], Bb + swz128(row * 128 + (ks * 2 + laneHi) * 16));
            }
#pragma unroll
            for (int mt = 0; mt < 4; mt++)
#pragma unroll
                for (int nt = 0; nt < 4; nt++) {
                    const int np = nt >> 1, half = nt & 1;
                    mma16816(acc[mt][nt], a[mt], b[np][half], b[np][2 + half]);
                }
        }
    }

    // epilogue: acc -> out with bias
    const int gq = lane >> 2, rq = lane & 3;
#pragma unroll
    for (int mt = 0; mt < 4; mt++) {
#pragma unroll
        for (int nt = 0; nt < 4; nt++) {
            int m = M0 + warp_m + mt * 16 + gq;
            int n = N0 + warp_n + nt * 8 + rq * 2;
            float2 bv = *(const float2*)&bias[n];
            float2 v0, v1;
            v0.x = acc[mt][nt][0] + bv.x;
            v0.y = acc[mt][nt][1] + bv.y;
            v1.x = acc[mt][nt][2] + bv.x;
            v1.y = acc[mt][nt][3] + bv.y;
            *(float2*)&out[(size_t)m * Ndim + n] = v0;
            *(float2*)&out[(size_t)(m + 8) * Ndim + n] = v1;
        }
    }
}

// ============================================================
// launch
// ============================================================
extern "C" void kernel_launch(void* const* d_in, const int* in_sizes, int n_in,
                              void* d_out, int out_size) {
    const float* x      = (const float*)d_in[0];
    const float* weight = (const float*)d_in[1];
    const float* bias   = (const float*)d_in[2];
    const float* downs  = (const float*)d_in[3];
    const float* ups    = (const float*)d_in[4];
    const float* scales = (const float*)d_in[5];
    float* out = (float*)d_out;

    cudaFuncSetAttribute(k_gemm, cudaFuncAttributeMaxDynamicSharedMemorySize, GEMM_SMEM);
    cudaFuncSetAttribute(k_weff_mma, cudaFuncAttributeMaxDynamicSharedMemorySize, WF_SMEM);

    k_prep2<<<PREP2_BLOCKS, 256>>>(x, downs, ups, scales);
    k_weff_mma<<<dim3(Kdim / 128, Ndim / 128), 256, WF_SMEM>>>(weight);
    k_gemm<<<dim3(Ndim / 128, Mdim / 128), 256, GEMM_SMEM>>>(bias, out);
}